// round 1
// baseline (speedup 1.0000x reference)
#include <cuda_runtime.h>
#include <math.h>

#define NNODES 100000
#define NGRAPH 256
#define NCLASS 10
#define NEG 0.2f
#define MAXE 1300000

// ---------------- scratch (static device globals; no allocation) ----------------
__device__ float g_H[NNODES * 64];      // h = x @ W for current layer
__device__ float g_A[NNODES * 64];      // layer output ping
__device__ float g_B[NNODES * 64];      // layer output pong
__device__ float g_s[NNODES];
__device__ float g_d[NNODES];
__device__ float g_m[NNODES];           // per-dst max logit
__device__ float g_den[NNODES];         // per-dst sum exp
__device__ float g_logit[MAXE];
__device__ float g_ex[MAXE];
__device__ float g_pool[NGRAPH * 64];

__device__ __forceinline__ float lrelu(float x) { return x > 0.f ? x : NEG * x; }

// atomic float max valid for mixed signs (non-NaN), init -inf or any valid value
__device__ __forceinline__ void atomicMaxF(float* a, float v) {
    if (v >= 0.f) atomicMax((int*)a, __float_as_int(v));
    else          atomicMin((unsigned int*)a, __float_as_uint(v));
}

// ---------------- kernels ----------------

// H[n,f] = sum_k X[n,k] * W[k,f]
template <int FIN, int FOUT>
__global__ void k_gemm(const float* __restrict__ X, const float* __restrict__ W,
                       float* __restrict__ H) {
    int idx = blockIdx.x * blockDim.x + threadIdx.x;
    if (idx >= NNODES * FOUT) return;
    int n = idx / FOUT, f = idx % FOUT;
    const float* xr = X + (long)n * FIN;
    float acc = 0.f;
#pragma unroll
    for (int k = 0; k < FIN; k++) acc = fmaf(xr[k], W[k * FOUT + f], acc);
    H[idx] = acc;
}

// s[n] = h[n].a_src, d[n] = h[n].a_dst, m[n] = lrelu(s+d) (self-loop logit init)
template <int FOUT>
__global__ void k_sd(const float* __restrict__ H, const float* __restrict__ asrc,
                     const float* __restrict__ adst) {
    int t = blockIdx.x * blockDim.x + threadIdx.x;
    int n = t >> 5, lane = t & 31;
    if (n >= NNODES) return;
    float s = 0.f, d = 0.f;
#pragma unroll
    for (int f = lane; f < FOUT; f += 32) {
        float h = H[n * FOUT + f];
        s = fmaf(h, asrc[f], s);
        d = fmaf(h, adst[f], d);
    }
#pragma unroll
    for (int o = 16; o > 0; o >>= 1) {
        s += __shfl_xor_sync(0xffffffffu, s, o);
        d += __shfl_xor_sync(0xffffffffu, d, o);
    }
    if (lane == 0) {
        g_s[n] = s;
        g_d[n] = d;
        g_m[n] = lrelu(s + d);
    }
}

// edge pass 1: logits + segment max
__global__ void k_e1(const int* __restrict__ src, const int* __restrict__ dst, int E) {
    int e = blockIdx.x * blockDim.x + threadIdx.x;
    if (e >= E) return;
    float l = lrelu(g_s[src[e]] + g_d[dst[e]]);
    g_logit[e] = l;
    atomicMaxF(&g_m[dst[e]], l);
}

// denom init with self-loop exp term
__global__ void k_selfden() {
    int n = blockIdx.x * blockDim.x + threadIdx.x;
    if (n >= NNODES) return;
    g_den[n] = __expf(lrelu(g_s[n] + g_d[n]) - g_m[n]);
}

// edge pass 2: exp + segment sum
__global__ void k_e2(const int* __restrict__ dst, int E) {
    int e = blockIdx.x * blockDim.x + threadIdx.x;
    if (e >= E) return;
    int t = dst[e];
    float ex = __expf(g_logit[e] - g_m[t]);
    g_ex[e] = ex;
    atomicAdd(&g_den[t], ex);
}

// out init with self-loop contribution: out[n] = alpha_self * h[n]
template <int FOUT>
__global__ void k_selfout(const float* __restrict__ H, float* __restrict__ OUT) {
    int idx = blockIdx.x * blockDim.x + threadIdx.x;
    if (idx >= NNODES * FOUT) return;
    int n = idx / FOUT;
    float w = __expf(lrelu(g_s[n] + g_d[n]) - g_m[n]) / (g_den[n] + 1e-16f);
    OUT[idx] = w * H[idx];
}

// edge pass 3: out[dst] += alpha * h[src]  (vectorized f32x4 L2 reductions)
template <int FOUT>
__global__ void k_e3(const int* __restrict__ src, const int* __restrict__ dst,
                     const float* __restrict__ H, float* __restrict__ OUT, int E) {
    constexpr int Q = FOUT / 4;
    int idx = blockIdx.x * blockDim.x + threadIdx.x;
    if (idx >= E * Q) return;
    int e = idx / Q, q = idx % Q;
    int s = src[e], t = dst[e];
    float w = g_ex[e] / (g_den[t] + 1e-16f);
    float4 h = *reinterpret_cast<const float4*>(H + (long)s * FOUT + q * 4);
    float* p = OUT + (long)t * FOUT + q * 4;
    asm volatile("red.global.add.v4.f32 [%0], {%1,%2,%3,%4};"
                 :: "l"(p), "f"(w * h.x), "f"(w * h.y), "f"(w * h.z), "f"(w * h.w)
                 : "memory");
}

// out = relu(out + b)
template <int FOUT>
__global__ void k_fin(float* __restrict__ OUT, const float* __restrict__ b) {
    int idx = blockIdx.x * blockDim.x + threadIdx.x;
    if (idx >= NNODES * FOUT) return;
    OUT[idx] = fmaxf(OUT[idx] + b[idx % FOUT], 0.f);
}

__global__ void k_poolinit() {
    int idx = blockIdx.x * blockDim.x + threadIdx.x;
    if (idx < NGRAPH * 64) g_pool[idx] = 0.f;  // inputs are post-relu (>=0)
}

// global max pool: values >= 0 so int-bit atomicMax is order-preserving
__global__ void k_pool(const float* __restrict__ X, const int* __restrict__ batch) {
    int idx = blockIdx.x * blockDim.x + threadIdx.x;
    if (idx >= NNODES * 64) return;
    int n = idx >> 6, f = idx & 63;
    atomicMax((int*)&g_pool[batch[n] * 64 + f], __float_as_int(X[idx]));
}

// FC + log_softmax; one block (64 threads) per graph
__global__ void k_fc(const float* __restrict__ fcw, const float* __restrict__ fcb,
                     float* __restrict__ out) {
    int g = blockIdx.x;
    int t = threadIdx.x;
    __shared__ float p[64];
    __shared__ float lg[NCLASS];
    __shared__ float red[2];
    p[t] = g_pool[g * 64 + t];
    __syncthreads();
    if (t < NCLASS) {
        float acc = fcb[t];
#pragma unroll
        for (int k = 0; k < 64; k++) acc = fmaf(p[k], fcw[k * NCLASS + t], acc);
        lg[t] = acc;
    }
    __syncthreads();
    if (t == 0) {
        float mx = lg[0];
#pragma unroll
        for (int i = 1; i < NCLASS; i++) mx = fmaxf(mx, lg[i]);
        float se = 0.f;
#pragma unroll
        for (int i = 0; i < NCLASS; i++) se += __expf(lg[i] - mx);
        red[0] = mx;
        red[1] = logf(se);
    }
    __syncthreads();
    if (t < NCLASS) out[g * NCLASS + t] = lg[t] - red[0] - red[1];
}

// ---------------- host ----------------

template <int FIN, int FOUT>
static void run_layer(const float* X, const float* W, const float* asrc, const float* adst,
                      const float* bb, float* H, float* OUT,
                      const int* srcp, const int* dstp, int E) {
    const int NT = 256;
    k_gemm<FIN, FOUT><<<(NNODES * FOUT + NT - 1) / NT, NT>>>(X, W, H);
    k_sd<FOUT><<<(NNODES * 32 + NT - 1) / NT, NT>>>(H, asrc, adst);
    k_e1<<<(E + NT - 1) / NT, NT>>>(srcp, dstp, E);
    k_selfden<<<(NNODES + NT - 1) / NT, NT>>>();
    k_e2<<<(E + NT - 1) / NT, NT>>>(dstp, E);
    k_selfout<FOUT><<<(NNODES * FOUT + NT - 1) / NT, NT>>>(H, OUT);
    k_e3<FOUT><<<(E * (FOUT / 4) + NT - 1) / NT, NT>>>(srcp, dstp, H, OUT, E);
    k_fin<FOUT><<<(NNODES * FOUT + NT - 1) / NT, NT>>>(OUT, bb);
}

extern "C" void kernel_launch(void* const* d_in, const int* in_sizes, int n_in,
                              void* d_out, int out_size) {
    const float* x     = (const float*)d_in[0];
    const int*   ei    = (const int*)d_in[1];
    const int*   batch = (const int*)d_in[2];
    const float* W1 = (const float*)d_in[3];
    const float* a1s = (const float*)d_in[4];
    const float* a1d = (const float*)d_in[5];
    const float* b1 = (const float*)d_in[6];
    const float* W2 = (const float*)d_in[7];
    const float* a2s = (const float*)d_in[8];
    const float* a2d = (const float*)d_in[9];
    const float* b2 = (const float*)d_in[10];
    const float* W3 = (const float*)d_in[11];
    const float* a3s = (const float*)d_in[12];
    const float* a3d = (const float*)d_in[13];
    const float* b3 = (const float*)d_in[14];
    const float* fcw = (const float*)d_in[15];
    const float* fcb = (const float*)d_in[16];
    float* out = (float*)d_out;

    int E = in_sizes[1] / 2;
    const int* srcp = ei;
    const int* dstp = ei + E;

    float *H, *A, *B;
    cudaGetSymbolAddress((void**)&H, g_H);
    cudaGetSymbolAddress((void**)&A, g_A);
    cudaGetSymbolAddress((void**)&B, g_B);

    run_layer<128, 16>(x, W1, a1s, a1d, b1, H, A, srcp, dstp, E);
    run_layer<16, 32>(A, W2, a2s, a2d, b2, H, B, srcp, dstp, E);
    run_layer<32, 64>(B, W3, a3s, a3d, b3, H, A, srcp, dstp, E);

    const int NT = 256;
    k_poolinit<<<(NGRAPH * 64 + NT - 1) / NT, NT>>>();
    k_pool<<<(NNODES * 64 + NT - 1) / NT, NT>>>(A, batch);
    k_fc<<<NGRAPH, 64>>>(fcw, fcb, out);
}

// round 2
// speedup vs baseline: 1.2983x; 1.2983x over previous
#include <cuda_runtime.h>
#include <math.h>

#define NNODES 100000
#define NGRAPH 256
#define NCLASS 10
#define NEG 0.2f
#define MAXE 1300000
#define SCANT 1024
#define CHUNK ((NNODES + SCANT - 1) / SCANT)   // 98

// ---------------- scratch (static device globals; no allocation) ----------------
__device__ float g_H[NNODES * 64];
__device__ float g_A[NNODES * 64];
__device__ float g_B[NNODES * 64];
__device__ float g_s[NNODES];
__device__ float g_d[NNODES];
__device__ float g_pool[NGRAPH * 64];
__device__ int   g_cnt[NNODES];
__device__ int   g_rowstart[NNODES + 1];
__device__ int   g_rowcur[NNODES];
__device__ int   g_csrc[MAXE];
__device__ int   g_tsum[SCANT];

__device__ __forceinline__ float lrelu(float x) { return x > 0.f ? x : NEG * x; }

// ---------------- CSR build ----------------

__global__ void k_zero_cnt() {
    int n = blockIdx.x * blockDim.x + threadIdx.x;
    if (n < NNODES) g_cnt[n] = 0;
}

__global__ void k_hist(const int* __restrict__ dst, int E) {
    int e = blockIdx.x * blockDim.x + threadIdx.x;
    if (e < E) atomicAdd(&g_cnt[dst[e]], 1);
}

__global__ void k_scanA() {
    int t = blockIdx.x * blockDim.x + threadIdx.x;   // 0..1023
    int beg = t * CHUNK, end = min(beg + CHUNK, NNODES);
    int s = 0;
    for (int i = beg; i < end; i++) s += g_cnt[i];
    g_tsum[t] = s;
}

__global__ void k_scanB() {  // one block, SCANT threads: exclusive scan of g_tsum
    __shared__ int sd[SCANT];
    int t = threadIdx.x;
    int orig = g_tsum[t];
    sd[t] = orig;
    __syncthreads();
    for (int off = 1; off < SCANT; off <<= 1) {
        int v = (t >= off) ? sd[t - off] : 0;
        __syncthreads();
        sd[t] += v;
        __syncthreads();
    }
    g_tsum[t] = sd[t] - orig;   // exclusive
}

__global__ void k_scanC() {
    int t = blockIdx.x * blockDim.x + threadIdx.x;
    int beg = t * CHUNK, end = min(beg + CHUNK, NNODES);
    int off = g_tsum[t];
    for (int i = beg; i < end; i++) {
        g_rowstart[i] = off;
        g_rowcur[i] = off;
        off += g_cnt[i];
    }
    if (t == SCANT - 1) g_rowstart[NNODES] = off;
}

__global__ void k_scatter(const int* __restrict__ src, const int* __restrict__ dst, int E) {
    int e = blockIdx.x * blockDim.x + threadIdx.x;
    if (e >= E) return;
    int pos = atomicAdd(&g_rowcur[dst[e]], 1);
    g_csrc[pos] = src[e];
}

// ---------------- GEMM ----------------

// layer 1: smem-tiled, 32 nodes per 256-thread block, FIN=128, FOUT=16
__global__ void k_gemm1(const float* __restrict__ X, const float* __restrict__ W,
                        float* __restrict__ H) {
    __shared__ float sx[32 * 128];
    __shared__ float sw[128 * 16];
    int tid = threadIdx.x;
    long base = (long)blockIdx.x * 32 * 128;
    // coalesced float4 loads of 32 rows of x
    const float4* xg = reinterpret_cast<const float4*>(X + base);
    float4* xs = reinterpret_cast<float4*>(sx);
#pragma unroll
    for (int i = tid; i < 32 * 128 / 4; i += 256) xs[i] = xg[i];
#pragma unroll
    for (int i = tid; i < 128 * 16; i += 256) sw[i] = W[i];
    __syncthreads();
#pragma unroll
    for (int r = 0; r < 2; r++) {
        int o = tid + r * 256;
        int n = o >> 4, f = o & 15;
        float acc = 0.f;
#pragma unroll
        for (int k = 0; k < 128; k++) acc = fmaf(sx[n * 128 + k], sw[k * 16 + f], acc);
        H[(long)blockIdx.x * 512 + o] = acc;
    }
}

// layers 2/3: one thread per (n, f)
template <int FIN, int FOUT>
__global__ void k_gemm(const float* __restrict__ X, const float* __restrict__ W,
                       float* __restrict__ H) {
    int idx = blockIdx.x * blockDim.x + threadIdx.x;
    if (idx >= NNODES * FOUT) return;
    int n = idx / FOUT, f = idx % FOUT;
    const float* xr = X + (long)n * FIN;
    float acc = 0.f;
#pragma unroll
    for (int k = 0; k < FIN; k++) acc = fmaf(xr[k], W[k * FOUT + f], acc);
    H[idx] = acc;
}

// s[n] = h[n].a_src, d[n] = h[n].a_dst  (warp per node)
template <int FOUT>
__global__ void k_sd(const float* __restrict__ H, const float* __restrict__ asrc,
                     const float* __restrict__ adst) {
    int t = blockIdx.x * blockDim.x + threadIdx.x;
    int n = t >> 5, lane = t & 31;
    if (n >= NNODES) return;
    float s = 0.f, d = 0.f;
#pragma unroll
    for (int f = lane; f < FOUT; f += 32) {
        float h = H[n * FOUT + f];
        s = fmaf(h, asrc[f], s);
        d = fmaf(h, adst[f], d);
    }
#pragma unroll
    for (int o = 16; o > 0; o >>= 1) {
        s += __shfl_xor_sync(0xffffffffu, s, o);
        d += __shfl_xor_sync(0xffffffffu, d, o);
    }
    if (lane == 0) { g_s[n] = s; g_d[n] = d; }
}

// ---------------- fused GAT aggregation: warp per dst node, no atomics ----------------
// out[n] = relu( (sum_e ex_e * h[src_e] + ex_self * h[n]) / (den + 1e-16) + b )
template <int FOUT>
__global__ void k_layer(const float* __restrict__ H, const float* __restrict__ b,
                        float* __restrict__ OUT) {
    constexpr int FPL = (FOUT + 31) / 32;   // features per lane
    int t = blockIdx.x * blockDim.x + threadIdx.x;
    int n = t >> 5, lane = t & 31;
    if (n >= NNODES) return;

    float d_n = g_d[n];
    float selfl = lrelu(g_s[n] + d_n);
    int beg = g_rowstart[n], end = g_rowstart[n + 1];

    // pass 1: segment max (lane-parallel)
    float m = selfl;
    for (int j = beg + lane; j < end; j += 32)
        m = fmaxf(m, lrelu(g_s[g_csrc[j]] + d_n));
#pragma unroll
    for (int o = 16; o > 0; o >>= 1)
        m = fmaxf(m, __shfl_xor_sync(0xffffffffu, m, o));

    // pass 2: sequential over edges; all lanes compute same w (broadcast loads)
    float den = __expf(selfl - m);
    float acc[FPL];
#pragma unroll
    for (int q = 0; q < FPL; q++) acc[q] = 0.f;

    for (int j = beg; j < end; j++) {
        int s = g_csrc[j];
        float w = __expf(lrelu(g_s[s] + d_n) - m);
        den += w;
        const float* hr = H + (long)s * FOUT;
#pragma unroll
        for (int q = 0; q < FPL; q++) {
            int f = q * 32 + lane;
            if (f < FOUT) acc[q] = fmaf(w, hr[f], acc[q]);
        }
    }

    // self contribution + normalize + bias + relu
    float wself = __expf(selfl - m);
    float inv = 1.f / (den + 1e-16f);
    const float* hn = H + (long)n * FOUT;
#pragma unroll
    for (int q = 0; q < FPL; q++) {
        int f = q * 32 + lane;
        if (f < FOUT) {
            float v = fmaf(wself, hn[f], acc[q]) * inv + b[f];
            OUT[(long)n * FOUT + f] = fmaxf(v, 0.f);
        }
    }
}

// ---------------- pooling: one block per graph (batch sorted), no atomics ----------------
__global__ void k_pool(const float* __restrict__ X, const int* __restrict__ batch) {
    int g = blockIdx.x;
    __shared__ int lohi[2];
    if (threadIdx.x < 2) {
        int target = g + threadIdx.x;     // lower_bound(batch, target)
        int lo = 0, hi = NNODES;
        while (lo < hi) {
            int mid = (lo + hi) >> 1;
            if (batch[mid] < target) lo = mid + 1; else hi = mid;
        }
        lohi[threadIdx.x] = lo;
    }
    __syncthreads();
    int f = threadIdx.x & 63, grp = threadIdx.x >> 6;
    float v = 0.f;   // inputs post-relu (>=0), segments non-empty
    for (int n = lohi[0] + grp; n < lohi[1]; n += 4)
        v = fmaxf(v, X[(long)n * 64 + f]);
    __shared__ float sm[256];
    sm[threadIdx.x] = v;
    __syncthreads();
    if (grp == 0)
        g_pool[g * 64 + f] = fmaxf(fmaxf(sm[f], sm[f + 64]),
                                   fmaxf(sm[f + 128], sm[f + 192]));
}

// FC + log_softmax; one block (64 threads) per graph
__global__ void k_fc(const float* __restrict__ fcw, const float* __restrict__ fcb,
                     float* __restrict__ out) {
    int g = blockIdx.x;
    int t = threadIdx.x;
    __shared__ float p[64];
    __shared__ float lg[NCLASS];
    __shared__ float red[2];
    p[t] = g_pool[g * 64 + t];
    __syncthreads();
    if (t < NCLASS) {
        float acc = fcb[t];
#pragma unroll
        for (int k = 0; k < 64; k++) acc = fmaf(p[k], fcw[k * NCLASS + t], acc);
        lg[t] = acc;
    }
    __syncthreads();
    if (t == 0) {
        float mx = lg[0];
#pragma unroll
        for (int i = 1; i < NCLASS; i++) mx = fmaxf(mx, lg[i]);
        float se = 0.f;
#pragma unroll
        for (int i = 0; i < NCLASS; i++) se += __expf(lg[i] - mx);
        red[0] = mx;
        red[1] = logf(se);
    }
    __syncthreads();
    if (t < NCLASS) out[g * NCLASS + t] = lg[t] - red[0] - red[1];
}

// ---------------- host ----------------

extern "C" void kernel_launch(void* const* d_in, const int* in_sizes, int n_in,
                              void* d_out, int out_size) {
    const float* x     = (const float*)d_in[0];
    const int*   ei    = (const int*)d_in[1];
    const int*   batch = (const int*)d_in[2];
    const float* W1 = (const float*)d_in[3];
    const float* a1s = (const float*)d_in[4];
    const float* a1d = (const float*)d_in[5];
    const float* b1 = (const float*)d_in[6];
    const float* W2 = (const float*)d_in[7];
    const float* a2s = (const float*)d_in[8];
    const float* a2d = (const float*)d_in[9];
    const float* b2 = (const float*)d_in[10];
    const float* W3 = (const float*)d_in[11];
    const float* a3s = (const float*)d_in[12];
    const float* a3d = (const float*)d_in[13];
    const float* b3 = (const float*)d_in[14];
    const float* fcw = (const float*)d_in[15];
    const float* fcb = (const float*)d_in[16];
    float* out = (float*)d_out;

    int E = in_sizes[1] / 2;
    const int* srcp = ei;
    const int* dstp = ei + E;

    float *H, *A, *B;
    cudaGetSymbolAddress((void**)&H, g_H);
    cudaGetSymbolAddress((void**)&A, g_A);
    cudaGetSymbolAddress((void**)&B, g_B);

    const int NT = 256;
    // CSR build (dst-sorted)
    k_zero_cnt<<<(NNODES + NT - 1) / NT, NT>>>();
    k_hist<<<(E + NT - 1) / NT, NT>>>(dstp, E);
    k_scanA<<<SCANT / NT, NT>>>();
    k_scanB<<<1, SCANT>>>();
    k_scanC<<<SCANT / NT, NT>>>();
    k_scatter<<<(E + NT - 1) / NT, NT>>>(srcp, dstp, E);

    // layer 1: 128 -> 16
    k_gemm1<<<NNODES / 32, 256>>>(x, W1, H);
    k_sd<16><<<(NNODES * 32 + NT - 1) / NT, NT>>>(H, a1s, a1d);
    k_layer<16><<<(NNODES * 32 + NT - 1) / NT, NT>>>(H, b1, A);

    // layer 2: 16 -> 32
    k_gemm<16, 32><<<(NNODES * 32 + NT - 1) / NT, NT>>>(A, W2, H);
    k_sd<32><<<(NNODES * 32 + NT - 1) / NT, NT>>>(H, a2s, a2d);
    k_layer<32><<<(NNODES * 32 + NT - 1) / NT, NT>>>(H, b2, B);

    // layer 3: 32 -> 64
    k_gemm<32, 64><<<(NNODES * 64 + NT - 1) / NT, NT>>>(B, W3, H);
    k_sd<64><<<(NNODES * 32 + NT - 1) / NT, NT>>>(H, a3s, a3d);
    k_layer<64><<<(NNODES * 32 + NT - 1) / NT, NT>>>(H, b3, A);

    // pool + fc
    k_pool<<<NGRAPH, 256>>>(A, batch);
    k_fc<<<NGRAPH, 64>>>(fcw, fcb, out);
}

// round 3
// speedup vs baseline: 1.4567x; 1.1220x over previous
#include <cuda_runtime.h>
#include <math.h>

#define NNODES 100000
#define NGRAPH 256
#define NCLASS 10
#define NEG 0.2f
#define MAXE 1300000
#define SBLK 1024
#define NSB ((NNODES + SBLK - 1) / SBLK)   // 98

// ---------------- scratch (static device globals; no allocation) ----------------
__device__ float g_H[NNODES * 64];
__device__ float g_A[NNODES * 64];
__device__ float g_B[NNODES * 64];
__device__ float g_s[NNODES];
__device__ float g_d[NNODES];
__device__ float g_pool[NGRAPH * 64];
__device__ int   g_cnt[NNODES];
__device__ int   g_rowstart[NNODES + 1];
__device__ int   g_rowcur[NNODES];
__device__ int   g_csrc[MAXE];
__device__ int   g_bsum[128];

__device__ __forceinline__ float lrelu(float x) { return x > 0.f ? x : NEG * x; }

// ---------------- CSR build (fully parallel scan) ----------------

__global__ void k_zero_cnt() {
    int n = blockIdx.x * blockDim.x + threadIdx.x;
    if (n < NNODES) g_cnt[n] = 0;
}

__global__ void k_hist(const int* __restrict__ dst, int E) {
    int e = blockIdx.x * blockDim.x + threadIdx.x;
    if (e < E) atomicAdd(&g_cnt[dst[e]], 1);
}

// per-block exclusive scan of g_cnt -> g_rowstart (local), block totals -> g_bsum
__global__ void k_scan1() {
    __shared__ int sd[SBLK];
    int i = blockIdx.x * SBLK + threadIdx.x;
    int v = (i < NNODES) ? g_cnt[i] : 0;
    sd[threadIdx.x] = v;
    __syncthreads();
    for (int off = 1; off < SBLK; off <<= 1) {
        int t = (threadIdx.x >= off) ? sd[threadIdx.x - off] : 0;
        __syncthreads();
        sd[threadIdx.x] += t;
        __syncthreads();
    }
    if (i < NNODES) g_rowstart[i] = sd[threadIdx.x] - v;   // exclusive within block
    if (threadIdx.x == SBLK - 1) g_bsum[blockIdx.x] = sd[SBLK - 1];
}

// exclusive scan of the 98 block sums
__global__ void k_scan2() {
    __shared__ int sd[128];
    int t = threadIdx.x;
    int v = (t < NSB) ? g_bsum[t] : 0;
    sd[t] = v;
    __syncthreads();
    for (int off = 1; off < 128; off <<= 1) {
        int u = (t >= off) ? sd[t - off] : 0;
        __syncthreads();
        sd[t] += u;
        __syncthreads();
    }
    if (t < NSB) g_bsum[t] = sd[t] - v;
    if (t == 127) g_rowstart[NNODES] = sd[127];   // total edge count
}

__global__ void k_scan3() {
    int i = blockIdx.x * SBLK + threadIdx.x;
    if (i >= NNODES) return;
    int v = g_rowstart[i] + g_bsum[blockIdx.x];
    g_rowstart[i] = v;
    g_rowcur[i] = v;
}

__global__ void k_scatter(const int* __restrict__ src, const int* __restrict__ dst, int E) {
    int e = blockIdx.x * blockDim.x + threadIdx.x;
    if (e >= E) return;
    int pos = atomicAdd(&g_rowcur[dst[e]], 1);
    g_csrc[pos] = src[e];
}

// ---------------- GEMM: thread computes FOUT/TPN outputs of one node ----------------
template <int FIN, int FOUT, int TPN>
__global__ void __launch_bounds__(256) k_gemm(const float* __restrict__ X,
                                              const float* __restrict__ W,
                                              float* __restrict__ H) {
    constexpr int FO = FOUT / TPN;
    __shared__ float sw[FIN * FOUT];
    for (int i = threadIdx.x; i < FIN * FOUT; i += 256) sw[i] = W[i];
    __syncthreads();
    int t = blockIdx.x * 256 + threadIdx.x;
    int n = t / TPN, part = t % TPN;
    if (n >= NNODES) return;
    const float4* xr = reinterpret_cast<const float4*>(X + (long)n * FIN);
    float acc[FO];
#pragma unroll
    for (int q = 0; q < FO; q++) acc[q] = 0.f;
#pragma unroll
    for (int k4 = 0; k4 < FIN / 4; k4++) {
        float4 xv = xr[k4];
        const float* wr = sw + (k4 * 4) * FOUT + part * FO;
#pragma unroll
        for (int q = 0; q < FO; q++) acc[q] = fmaf(xv.x, wr[q], acc[q]);
#pragma unroll
        for (int q = 0; q < FO; q++) acc[q] = fmaf(xv.y, wr[FOUT + q], acc[q]);
#pragma unroll
        for (int q = 0; q < FO; q++) acc[q] = fmaf(xv.z, wr[2 * FOUT + q], acc[q]);
#pragma unroll
        for (int q = 0; q < FO; q++) acc[q] = fmaf(xv.w, wr[3 * FOUT + q], acc[q]);
    }
    float* hr = H + (long)n * FOUT + part * FO;
#pragma unroll
    for (int q = 0; q < FO; q++) hr[q] = acc[q];
}

// s[n] = h[n].a_src, d[n] = h[n].a_dst  (warp per node)
template <int FOUT>
__global__ void k_sd(const float* __restrict__ H, const float* __restrict__ asrc,
                     const float* __restrict__ adst) {
    int t = blockIdx.x * blockDim.x + threadIdx.x;
    int n = t >> 5, lane = t & 31;
    if (n >= NNODES) return;
    float s = 0.f, d = 0.f;
#pragma unroll
    for (int f = lane; f < FOUT; f += 32) {
        float h = H[n * FOUT + f];
        s = fmaf(h, asrc[f], s);
        d = fmaf(h, adst[f], d);
    }
#pragma unroll
    for (int o = 16; o > 0; o >>= 1) {
        s += __shfl_xor_sync(0xffffffffu, s, o);
        d += __shfl_xor_sync(0xffffffffu, d, o);
    }
    if (lane == 0) { g_s[n] = s; g_d[n] = d; }
}

// ---------------- fused GAT aggregation: warp per dst node, lane-parallel weights ----
template <int FOUT>
__global__ void __launch_bounds__(256) k_layer(const float* __restrict__ H,
                                               const float* __restrict__ b,
                                               float* __restrict__ OUT) {
    constexpr int FPL = FOUT > 32 ? FOUT / 32 : 1;   // features per lane
    constexpr int EPI = FOUT < 32 ? 32 / FOUT : 1;   // edges per inner step
    __shared__ int   ss[8][32];
    __shared__ float sw[8][32];
    int wid = threadIdx.x >> 5, lane = threadIdx.x & 31;
    int n = blockIdx.x * 8 + wid;
    if (n >= NNODES) return;

    float d_n = g_d[n];
    float selfl = lrelu(g_s[n] + d_n);
    int beg = g_rowstart[n], end = g_rowstart[n + 1];

    // pass 1: segment max (lane-parallel)
    float m = selfl;
    for (int j = beg + lane; j < end; j += 32)
        m = fmaxf(m, lrelu(g_s[g_csrc[j]] + d_n));
#pragma unroll
    for (int o = 16; o > 0; o >>= 1)
        m = fmaxf(m, fmaxf(m, __shfl_xor_sync(0xffffffffu, m, o)));

    // pass 2: lane-parallel weights staged in smem; broadcast aggregation
    float den = 0.f;
    float acc[FPL];
#pragma unroll
    for (int q = 0; q < FPL; q++) acc[q] = 0.f;
    int sub = lane / FOUT < EPI ? lane / FOUT : 0;   // 0..EPI-1
    int f0 = lane % (FOUT < 32 ? FOUT : 32);

    for (int cb = beg; cb < end; cb += 32) {
        int j = cb + lane;
        int s = 0;
        float w = 0.f;
        if (j < end) {
            s = g_csrc[j];
            w = __expf(lrelu(g_s[s] + d_n) - m);
        }
        den += w;
        ss[wid][lane] = s;
        sw[wid][lane] = w;
        __syncwarp();
        int cnt = min(32, end - cb);
        for (int k = sub; k < cnt; k += EPI) {
            float wk = sw[wid][k];
            long sk = ss[wid][k];
#pragma unroll
            for (int q = 0; q < FPL; q++)
                acc[q] = fmaf(wk, H[sk * FOUT + q * 32 + f0], acc[q]);
        }
        __syncwarp();
    }

    // reduce den across lanes
#pragma unroll
    for (int o = 16; o > 0; o >>= 1) den += __shfl_xor_sync(0xffffffffu, den, o);

    // combine edge-parallel halves (FOUT=16 case)
    if (EPI == 2) acc[0] += __shfl_xor_sync(0xffffffffu, acc[0], 16);

    float wself = __expf(selfl - m);
    den += wself;
    float inv = 1.f / (den + 1e-16f);
    const float* hn = H + (long)n * FOUT;
    if (lane < (FOUT < 32 ? FOUT : 32)) {
#pragma unroll
        for (int q = 0; q < FPL; q++) {
            int f = q * 32 + f0;
            float v = fmaf(wself, hn[f], acc[q]) * inv + b[f];
            OUT[(long)n * FOUT + f] = fmaxf(v, 0.f);
        }
    }
}

// ---------------- pooling: one block per graph (batch sorted), no atomics ----------------
__global__ void k_pool(const float* __restrict__ X, const int* __restrict__ batch) {
    int g = blockIdx.x;
    __shared__ int lohi[2];
    if (threadIdx.x < 2) {
        int target = g + threadIdx.x;
        int lo = 0, hi = NNODES;
        while (lo < hi) {
            int mid = (lo + hi) >> 1;
            if (batch[mid] < target) lo = mid + 1; else hi = mid;
        }
        lohi[threadIdx.x] = lo;
    }
    __syncthreads();
    int f = threadIdx.x & 63, grp = threadIdx.x >> 6;
    float v = 0.f;
    for (int n = lohi[0] + grp; n < lohi[1]; n += 4)
        v = fmaxf(v, X[(long)n * 64 + f]);
    __shared__ float sm[256];
    sm[threadIdx.x] = v;
    __syncthreads();
    if (grp == 0)
        g_pool[g * 64 + f] = fmaxf(fmaxf(sm[f], sm[f + 64]),
                                   fmaxf(sm[f + 128], sm[f + 192]));
}

// FC + log_softmax; one block (64 threads) per graph
__global__ void k_fc(const float* __restrict__ fcw, const float* __restrict__ fcb,
                     float* __restrict__ out) {
    int g = blockIdx.x;
    int t = threadIdx.x;
    __shared__ float p[64];
    __shared__ float lg[NCLASS];
    __shared__ float red[2];
    p[t] = g_pool[g * 64 + t];
    __syncthreads();
    if (t < NCLASS) {
        float acc = fcb[t];
#pragma unroll
        for (int k = 0; k < 64; k++) acc = fmaf(p[k], fcw[k * NCLASS + t], acc);
        lg[t] = acc;
    }
    __syncthreads();
    if (t == 0) {
        float mx = lg[0];
#pragma unroll
        for (int i = 1; i < NCLASS; i++) mx = fmaxf(mx, lg[i]);
        float se = 0.f;
#pragma unroll
        for (int i = 0; i < NCLASS; i++) se += __expf(lg[i] - mx);
        red[0] = mx;
        red[1] = logf(se);
    }
    __syncthreads();
    if (t < NCLASS) out[g * NCLASS + t] = lg[t] - red[0] - red[1];
}

// ---------------- host ----------------

extern "C" void kernel_launch(void* const* d_in, const int* in_sizes, int n_in,
                              void* d_out, int out_size) {
    const float* x     = (const float*)d_in[0];
    const int*   ei    = (const int*)d_in[1];
    const int*   batch = (const int*)d_in[2];
    const float* W1 = (const float*)d_in[3];
    const float* a1s = (const float*)d_in[4];
    const float* a1d = (const float*)d_in[5];
    const float* b1 = (const float*)d_in[6];
    const float* W2 = (const float*)d_in[7];
    const float* a2s = (const float*)d_in[8];
    const float* a2d = (const float*)d_in[9];
    const float* b2 = (const float*)d_in[10];
    const float* W3 = (const float*)d_in[11];
    const float* a3s = (const float*)d_in[12];
    const float* a3d = (const float*)d_in[13];
    const float* b3 = (const float*)d_in[14];
    const float* fcw = (const float*)d_in[15];
    const float* fcb = (const float*)d_in[16];
    float* out = (float*)d_out;

    int E = in_sizes[1] / 2;
    const int* srcp = ei;
    const int* dstp = ei + E;

    float *H, *A, *B;
    cudaGetSymbolAddress((void**)&H, g_H);
    cudaGetSymbolAddress((void**)&A, g_A);
    cudaGetSymbolAddress((void**)&B, g_B);

    const int NT = 256;
    // CSR build (dst-sorted)
    k_zero_cnt<<<(NNODES + NT - 1) / NT, NT>>>();
    k_hist<<<(E + NT - 1) / NT, NT>>>(dstp, E);
    k_scan1<<<NSB, SBLK>>>();
    k_scan2<<<1, 128>>>();
    k_scan3<<<NSB, SBLK>>>();
    k_scatter<<<(E + NT - 1) / NT, NT>>>(srcp, dstp, E);

    // layer 1: 128 -> 16
    k_gemm<128, 16, 1><<<(NNODES + NT - 1) / NT, NT>>>(x, W1, H);
    k_sd<16><<<(NNODES * 32 + NT - 1) / NT, NT>>>(H, a1s, a1d);
    k_layer<16><<<(NNODES + 7) / 8, NT>>>(H, b1, A);

    // layer 2: 16 -> 32
    k_gemm<16, 32, 1><<<(NNODES + NT - 1) / NT, NT>>>(A, W2, H);
    k_sd<32><<<(NNODES * 32 + NT - 1) / NT, NT>>>(H, a2s, a2d);
    k_layer<32><<<(NNODES + 7) / 8, NT>>>(H, b2, B);

    // layer 3: 32 -> 64
    k_gemm<32, 64, 2><<<(NNODES * 2 + NT - 1) / NT, NT>>>(B, W3, H);
    k_sd<64><<<(NNODES * 32 + NT - 1) / NT, NT>>>(H, a3s, a3d);
    k_layer<64><<<(NNODES + 7) / 8, NT>>>(H, b3, A);

    // pool + fc
    k_pool<<<NGRAPH, NT>>>(A, batch);
    k_fc<<<NGRAPH, 64>>>(fcw, fcb, out);
}

// round 4
// speedup vs baseline: 1.7112x; 1.1747x over previous
#include <cuda_runtime.h>
#include <math.h>

#define NNODES 100000
#define NGRAPH 256
#define NCLASS 10
#define NEG 0.2f
#define MAXE 1300000
#define SBLK 1024
#define NSB ((NNODES + SBLK - 1) / SBLK)   // 98

// ---------------- scratch (static device globals; no allocation) ----------------
__device__ __align__(16) float g_H[NNODES * 64];
__device__ __align__(16) float g_A[NNODES * 64];
__device__ __align__(16) float g_B[NNODES * 64];
__device__ float g_s[NNODES];
__device__ float g_d[NNODES];
__device__ int   g_cnt[NNODES];
__device__ int   g_rowstart[NNODES + 1];
__device__ int   g_rowcur[NNODES];
__device__ int   g_csrc[MAXE];
__device__ volatile int g_aggr[NSB];
__device__ volatile int g_incl[NSB];
__device__ volatile int g_flag[NSB];

__device__ __forceinline__ float lrelu(float x) { return x > 0.f ? x : NEG * x; }

// ---------------- CSR build ----------------

__global__ void k_zero() {
    int n = blockIdx.x * blockDim.x + threadIdx.x;
    if (n < NNODES) g_cnt[n] = 0;
    if (n < NSB) g_flag[n] = 0;
}

__global__ void k_hist(const int* __restrict__ dst, int E) {
    int e = blockIdx.x * blockDim.x + threadIdx.x;
    if (e < E) atomicAdd(&g_cnt[dst[e]], 1);
}

// single-kernel exclusive scan with decoupled lookback (98 blocks, all resident)
__global__ void k_scan() {
    __shared__ int sd[SBLK];
    __shared__ int s_prefix;
    int b = blockIdx.x;
    int i = b * SBLK + threadIdx.x;
    int v = (i < NNODES) ? g_cnt[i] : 0;
    sd[threadIdx.x] = v;
    __syncthreads();
    for (int off = 1; off < SBLK; off <<= 1) {
        int t = (threadIdx.x >= off) ? sd[threadIdx.x - off] : 0;
        __syncthreads();
        sd[threadIdx.x] += t;
        __syncthreads();
    }
    if (threadIdx.x == 0) {
        int agg = sd[SBLK - 1];
        if (b == 0) {
            g_incl[0] = agg;
            __threadfence();
            g_flag[0] = 2;
            s_prefix = 0;
        } else {
            g_aggr[b] = agg;
            __threadfence();
            g_flag[b] = 1;
            int sum = 0, j = b - 1;
            while (true) {
                int f;
                while ((f = g_flag[j]) == 0) {}
                if (f == 2) { sum += g_incl[j]; break; }
                sum += g_aggr[j];
                j--;
            }
            g_incl[b] = sum + agg;
            __threadfence();
            g_flag[b] = 2;
            s_prefix = sum;
        }
    }
    __syncthreads();
    int ex = s_prefix + sd[threadIdx.x] - v;
    if (i < NNODES) { g_rowstart[i] = ex; g_rowcur[i] = ex; }
    if (i == NNODES - 1) g_rowstart[NNODES] = ex + v;
}

__global__ void k_scatter(const int* __restrict__ src, const int* __restrict__ dst, int E) {
    int e = blockIdx.x * blockDim.x + threadIdx.x;
    if (e >= E) return;
    int pos = atomicAdd(&g_rowcur[dst[e]], 1);
    g_csrc[pos] = src[e];
}

// ---------------- fused GEMM + attention coefficients ----------------
// H[n] = X[n] @ W ; g_s[n] = H[n].asrc ; g_d[n] = H[n].adst
template <int FIN, int FOUT, int TPN>
__global__ void __launch_bounds__(256) k_gemmsd(const float* __restrict__ X,
                                                const float* __restrict__ W,
                                                const float* __restrict__ asrc,
                                                const float* __restrict__ adst,
                                                float* __restrict__ H) {
    constexpr int FO = FOUT / TPN;
    __shared__ float sw[FIN * FOUT];
    __shared__ float sa[FOUT], sdv[FOUT];
    for (int i = threadIdx.x; i < FIN * FOUT; i += 256) sw[i] = W[i];
    if (threadIdx.x < FOUT) {
        sa[threadIdx.x] = asrc[threadIdx.x];
        sdv[threadIdx.x] = adst[threadIdx.x];
    }
    __syncthreads();
    int t = blockIdx.x * 256 + threadIdx.x;
    int n = t / TPN, part = t % TPN;
    bool valid = n < NNODES;
    int nc = valid ? n : NNODES - 1;
    const float4* xr = reinterpret_cast<const float4*>(X + (long)nc * FIN);
    float acc[FO];
#pragma unroll
    for (int q = 0; q < FO; q++) acc[q] = 0.f;
#pragma unroll
    for (int k4 = 0; k4 < FIN / 4; k4++) {
        float4 xv = xr[k4];
        const float* wr = sw + (k4 * 4) * FOUT + part * FO;
#pragma unroll
        for (int q = 0; q < FO; q++) acc[q] = fmaf(xv.x, wr[q], acc[q]);
#pragma unroll
        for (int q = 0; q < FO; q++) acc[q] = fmaf(xv.y, wr[FOUT + q], acc[q]);
#pragma unroll
        for (int q = 0; q < FO; q++) acc[q] = fmaf(xv.z, wr[2 * FOUT + q], acc[q]);
#pragma unroll
        for (int q = 0; q < FO; q++) acc[q] = fmaf(xv.w, wr[3 * FOUT + q], acc[q]);
    }
    if (valid) {
        float* hr = H + (long)n * FOUT + part * FO;
#pragma unroll
        for (int q = 0; q < FO; q++) hr[q] = acc[q];
    }
    float s = 0.f, d = 0.f;
#pragma unroll
    for (int q = 0; q < FO; q++) {
        s = fmaf(acc[q], sa[part * FO + q], s);
        d = fmaf(acc[q], sdv[part * FO + q], d);
    }
    if (TPN == 2) {
        s += __shfl_xor_sync(0xffffffffu, s, 1);
        d += __shfl_xor_sync(0xffffffffu, d, 1);
    }
    if (valid && part == 0) { g_s[n] = s; g_d[n] = d; }
}

// ---------------- fused GAT aggregation: warp per dst node ----------------
template <int FOUT>
__global__ void __launch_bounds__(256) k_layer(const float* __restrict__ H,
                                               const float* __restrict__ b,
                                               float* __restrict__ OUT) {
    constexpr int L = FOUT / 2;       // lanes per edge (float2 each)
    constexpr int EPI = 32 / L;       // edges processed in parallel
    __shared__ int   ss[8][32];
    __shared__ float sw[8][32];
    int wid = threadIdx.x >> 5, lane = threadIdx.x & 31;
    int n = blockIdx.x * 8 + wid;
    if (n >= NNODES) return;

    float d_n = g_d[n];
    float selfl = lrelu(g_s[n] + d_n);
    int beg = g_rowstart[n], end = g_rowstart[n + 1];
    int deg = end - beg;

    int sub = lane / L;
    int f0 = lane % L;
    float2 acc = make_float2(0.f, 0.f);
    float den = 0.f;
    float m;

    if (deg <= 32) {
        // fast path: single scattered gather of g_s, all in registers
        int s = 0;
        float l = -3.4e38f;
        if (lane < deg) {
            s = g_csrc[beg + lane];
            l = lrelu(g_s[s] + d_n);
        }
        m = fmaxf(l, selfl);
#pragma unroll
        for (int o = 16; o > 0; o >>= 1)
            m = fmaxf(m, __shfl_xor_sync(0xffffffffu, m, o));
        float w = (lane < deg) ? __expf(l - m) : 0.f;
        den = w;
        ss[wid][lane] = s;
        sw[wid][lane] = w;
        __syncwarp();
#pragma unroll 4
        for (int k = sub; k < deg; k += EPI) {
            float wk = sw[wid][k];
            long sk = ss[wid][k];
            float2 h = *reinterpret_cast<const float2*>(H + sk * FOUT + 2 * f0);
            acc.x = fmaf(wk, h.x, acc.x);
            acc.y = fmaf(wk, h.y, acc.y);
        }
        __syncwarp();
    } else {
        // rare path: chunked two-pass
        m = selfl;
        for (int j = beg + lane; j < end; j += 32)
            m = fmaxf(m, lrelu(g_s[g_csrc[j]] + d_n));
#pragma unroll
        for (int o = 16; o > 0; o >>= 1)
            m = fmaxf(m, __shfl_xor_sync(0xffffffffu, m, o));
        for (int cb = beg; cb < end; cb += 32) {
            int j = cb + lane;
            int s = 0;
            float w = 0.f;
            if (j < end) {
                s = g_csrc[j];
                w = __expf(lrelu(g_s[s] + d_n) - m);
            }
            den += w;
            ss[wid][lane] = s;
            sw[wid][lane] = w;
            __syncwarp();
            int cnt = min(32, end - cb);
#pragma unroll 4
            for (int k = sub; k < cnt; k += EPI) {
                float wk = sw[wid][k];
                long sk = ss[wid][k];
                float2 h = *reinterpret_cast<const float2*>(H + sk * FOUT + 2 * f0);
                acc.x = fmaf(wk, h.x, acc.x);
                acc.y = fmaf(wk, h.y, acc.y);
            }
            __syncwarp();
        }
    }

    // reduce den across lanes
#pragma unroll
    for (int o = 16; o > 0; o >>= 1) den += __shfl_xor_sync(0xffffffffu, den, o);
    // combine edge-parallel sub-groups
#pragma unroll
    for (int o = L; o < 32; o <<= 1) {
        acc.x += __shfl_xor_sync(0xffffffffu, acc.x, o);
        acc.y += __shfl_xor_sync(0xffffffffu, acc.y, o);
    }

    float wself = __expf(selfl - m);
    den += wself;
    float inv = 1.f / (den + 1e-16f);
    if (lane < L) {
        float2 hn = *reinterpret_cast<const float2*>(H + (long)n * FOUT + 2 * f0);
        float2 bb = reinterpret_cast<const float2*>(b)[f0];
        float vx = fmaf(wself, hn.x, acc.x) * inv + bb.x;
        float vy = fmaf(wself, hn.y, acc.y) * inv + bb.y;
        float2 o2 = make_float2(fmaxf(vx, 0.f), fmaxf(vy, 0.f));
        *reinterpret_cast<float2*>(OUT + (long)n * FOUT + 2 * f0) = o2;
    }
}

// ---------------- fused pool + FC + log_softmax: one block per graph ----------------
__global__ void k_poolfc(const float* __restrict__ X, const int* __restrict__ batch,
                         const float* __restrict__ fcw, const float* __restrict__ fcb,
                         float* __restrict__ out) {
    int g = blockIdx.x;
    int t = threadIdx.x;
    __shared__ int lohi[2];
    if (t < 2) {
        int target = g + t;
        int lo = 0, hi = NNODES;
        while (lo < hi) {
            int mid = (lo + hi) >> 1;
            if (batch[mid] < target) lo = mid + 1; else hi = mid;
        }
        lohi[t] = lo;
    }
    __syncthreads();
    int f = t & 63, grp = t >> 6;
    float v = 0.f;   // inputs post-relu (>=0), segments non-empty
    for (int n = lohi[0] + grp; n < lohi[1]; n += 4)
        v = fmaxf(v, X[(long)n * 64 + f]);
    __shared__ float sm[256];
    __shared__ float p[64];
    sm[t] = v;
    __syncthreads();
    if (grp == 0)
        p[f] = fmaxf(fmaxf(sm[f], sm[f + 64]), fmaxf(sm[f + 128], sm[f + 192]));
    __syncthreads();
    __shared__ float lg[NCLASS];
    __shared__ float red[2];
    if (t < NCLASS) {
        float acc = fcb[t];
#pragma unroll
        for (int k = 0; k < 64; k++) acc = fmaf(p[k], fcw[k * NCLASS + t], acc);
        lg[t] = acc;
    }
    __syncthreads();
    if (t == 0) {
        float mx = lg[0];
#pragma unroll
        for (int i = 1; i < NCLASS; i++) mx = fmaxf(mx, lg[i]);
        float se = 0.f;
#pragma unroll
        for (int i = 0; i < NCLASS; i++) se += __expf(lg[i] - mx);
        red[0] = mx;
        red[1] = logf(se);
    }
    __syncthreads();
    if (t < NCLASS) out[g * NCLASS + t] = lg[t] - red[0] - red[1];
}

// ---------------- host ----------------

extern "C" void kernel_launch(void* const* d_in, const int* in_sizes, int n_in,
                              void* d_out, int out_size) {
    const float* x     = (const float*)d_in[0];
    const int*   ei    = (const int*)d_in[1];
    const int*   batch = (const int*)d_in[2];
    const float* W1 = (const float*)d_in[3];
    const float* a1s = (const float*)d_in[4];
    const float* a1d = (const float*)d_in[5];
    const float* b1 = (const float*)d_in[6];
    const float* W2 = (const float*)d_in[7];
    const float* a2s = (const float*)d_in[8];
    const float* a2d = (const float*)d_in[9];
    const float* b2 = (const float*)d_in[10];
    const float* W3 = (const float*)d_in[11];
    const float* a3s = (const float*)d_in[12];
    const float* a3d = (const float*)d_in[13];
    const float* b3 = (const float*)d_in[14];
    const float* fcw = (const float*)d_in[15];
    const float* fcb = (const float*)d_in[16];
    float* out = (float*)d_out;

    int E = in_sizes[1] / 2;
    const int* srcp = ei;
    const int* dstp = ei + E;

    float *H, *A, *B;
    cudaGetSymbolAddress((void**)&H, g_H);
    cudaGetSymbolAddress((void**)&A, g_A);
    cudaGetSymbolAddress((void**)&B, g_B);

    const int NT = 256;
    // CSR build (dst-sorted)
    k_zero<<<(NNODES + NT - 1) / NT, NT>>>();
    k_hist<<<(E + NT - 1) / NT, NT>>>(dstp, E);
    k_scan<<<NSB, SBLK>>>();
    k_scatter<<<(E + NT - 1) / NT, NT>>>(srcp, dstp, E);

    // layer 1: 128 -> 16
    k_gemmsd<128, 16, 1><<<(NNODES + NT - 1) / NT, NT>>>(x, W1, a1s, a1d, H);
    k_layer<16><<<(NNODES + 7) / 8, NT>>>(H, b1, A);

    // layer 2: 16 -> 32
    k_gemmsd<16, 32, 1><<<(NNODES + NT - 1) / NT, NT>>>(A, W2, a2s, a2d, H);
    k_layer<32><<<(NNODES + 7) / 8, NT>>>(H, b2, B);

    // layer 3: 32 -> 64
    k_gemmsd<32, 64, 2><<<(NNODES * 2 + NT - 1) / NT, NT>>>(B, W3, a3s, a3d, H);
    k_layer<64><<<(NNODES + 7) / 8, NT>>>(H, b3, A);

    // pool + fc + log_softmax
    k_poolfc<<<NGRAPH, NT>>>(A, batch, fcw, fcb, out);
}